// round 13
// baseline (speedup 1.0000x reference)
#include <cuda_runtime.h>
#include <cuda_bf16.h>
#include <cstdint>

using bf16 = __nv_bfloat16;

#define N_NODES 50000
#define N_PAD   50048
#define E_EDGES 800000
#define F_IN    128
#define HID     256
#define SCAN_BLOCKS 49

__device__ bf16  g_xhi [(size_t)N_PAD * F_IN];
__device__ bf16  g_xlo [(size_t)N_PAD * F_IN];
__device__ bf16  g_aghi[(size_t)N_PAD * HID];
__device__ bf16  g_aglo[(size_t)N_PAD * HID];
__device__ bf16  g_h1hi[(size_t)N_PAD * HID];
__device__ bf16  g_h1lo[(size_t)N_PAD * HID];
__device__ bf16  g_h2hi[(size_t)N_PAD * HID];
__device__ bf16  g_h2lo[(size_t)N_PAD * HID];
__device__ float g_f32 [(size_t)N_PAD * HID];
__device__ bf16  g_wthi[458752];
__device__ bf16  g_wtlo[458752];
__device__ int   g_deg[N_NODES];
__device__ int   g_rowptr[N_NODES + 1];
__device__ int   g_cursor[N_NODES];
__device__ int   g_csrsrc[E_EDGES];
__device__ int   g_flag[SCAN_BLOCKS + 1];
__device__ int   g_pref[SCAN_BLOCKS + 1];

// ---------------- PTX helpers ----------------
__device__ __forceinline__ uint32_t smem_u32(const void* p) {
    uint32_t a;
    asm("{ .reg .u64 t; cvta.to.shared.u64 t, %1; cvt.u32.u64 %0, t; }" : "=r"(a) : "l"(p));
    return a;
}
__device__ __forceinline__ void ldsm4(uint32_t* r, uint32_t addr) {
    asm volatile("ldmatrix.sync.aligned.m8n8.x4.shared.b16 {%0,%1,%2,%3}, [%4];"
                 : "=r"(r[0]), "=r"(r[1]), "=r"(r[2]), "=r"(r[3]) : "r"(addr));
}
__device__ __forceinline__ void mma_bf16(float* c, const uint32_t* a, const uint32_t* b) {
    asm volatile("mma.sync.aligned.m16n8k16.row.col.f32.bf16.bf16.f32 "
                 "{%0,%1,%2,%3}, {%4,%5,%6,%7}, {%8,%9}, {%0,%1,%2,%3};"
                 : "+f"(c[0]), "+f"(c[1]), "+f"(c[2]), "+f"(c[3])
                 : "r"(a[0]), "r"(a[1]), "r"(a[2]), "r"(a[3]), "r"(b[0]), "r"(b[1]));
}
__device__ __forceinline__ void cpa(uint32_t d, const void* s) {
    asm volatile("cp.async.cg.shared.global [%0], [%1], 16;" :: "r"(d), "l"(s));
}
__device__ __forceinline__ void split2(float v, bf16& h, bf16& l) {
    h = __float2bfloat16(v);
    l = __float2bfloat16(v - __bfloat162float(h));
}

// ---------------- CSR build ----------------
__device__ __forceinline__ int detect_is64(const void* ei) {
    __shared__ int s64;
    if (threadIdx.x == 0) {
        const long long* p = (const long long*)ei;
        int ok = 1;
        #pragma unroll 1
        for (int k = 0; k < 128; k++) {
            long long v = p[k];
            if (v < 0 || v >= N_NODES) { ok = 0; break; }
        }
        s64 = ok;
    }
    __syncthreads();
    return s64;
}
__device__ __forceinline__ int load_edge(const void* ei, int idx, int is64) {
    return is64 ? (int)((const long long*)ei)[idx] : ((const int*)ei)[idx];
}

__global__ void hist_kernel(const void* ei) {
    int is64 = detect_is64(ei);
    int e = blockIdx.x * blockDim.x + threadIdx.x;
    if (e < E_EDGES) atomicAdd(&g_deg[load_edge(ei, E_EDGES + e, is64)], 1);
}

__global__ __launch_bounds__(1024)
void scan_kernel() {
    __shared__ int wsum[32];
    __shared__ int s_pref;
    int tid = threadIdx.x, b = blockIdx.x, wid = tid >> 5, lane = tid & 31;
    int i = b * 1024 + tid;
    int v = (i < N_NODES) ? g_deg[i] : 0;
    int incl = v;
    #pragma unroll
    for (int off = 1; off < 32; off <<= 1) {
        int t = __shfl_up_sync(~0u, incl, off);
        if (lane >= off) incl += t;
    }
    if (lane == 31) wsum[wid] = incl;
    __syncthreads();
    if (tid < 32) {
        int x = wsum[tid];
        #pragma unroll
        for (int off = 1; off < 32; off <<= 1) {
            int t = __shfl_up_sync(~0u, x, off);
            if (tid >= off) x += t;
        }
        wsum[tid] = x;
    }
    __syncthreads();
    int excl = (wid ? wsum[wid - 1] : 0) + incl - v;
    if (tid == 0) {
        int total = wsum[31], p = 0;
        if (b > 0) {
            while (atomicAdd(&g_flag[b - 1], 0) == 0) { }
            p = *((volatile int*)&g_pref[b - 1]);
        }
        *((volatile int*)&g_pref[b]) = p + total;
        __threadfence();
        atomicExch(&g_flag[b], 1);
        s_pref = p;
    }
    __syncthreads();
    if (i < N_NODES) { int r = s_pref + excl; g_rowptr[i] = r; g_cursor[i] = r; }
    if (b == 0 && tid == 0) g_rowptr[N_NODES] = E_EDGES;
}

__global__ void scatter_kernel(const void* ei) {
    int is64 = detect_is64(ei);
    int e = blockIdx.x * blockDim.x + threadIdx.x;
    if (e < E_EDGES) {
        int s = load_edge(ei, e, is64);
        int d = load_edge(ei, E_EDGES + e, is64);
        g_csrsrc[atomicAdd(&g_cursor[d], 1)] = s;
    }
}

__global__ void reset_kernel() {
    int i = blockIdx.x * blockDim.x + threadIdx.x;
    if (i < N_NODES) g_deg[i] = 0;
    if (i <= SCAN_BLOCKS) { g_flag[i] = 0; g_pref[i] = 0; }
}

// ---------------- conv: weights transpose+split AND x split (one kernel) ----
struct ConvW { const float* W[8]; int off[8]; int K[8]; };
#define XBLKS 6250         // 1.6M float4 / 256
__global__ void conv_kernel(ConvW P, const float4* __restrict__ x4) {
    int bid = blockIdx.x;
    if (bid < 512) {
        int mat = bid >> 6, sub = bid & 63;
        int n0 = (sub & 7) * 32, k0 = (sub >> 3) * 32, Kd = P.K[mat];
        if (k0 >= Kd) return;
        __shared__ float t[32][33];
        int tx = threadIdx.x & 31, ty = threadIdx.x >> 5;
        #pragma unroll
        for (int q = 0; q < 4; q++)
            t[ty + q * 8][tx] = P.W[mat][(size_t)(k0 + ty + q * 8) * 256 + n0 + tx];
        __syncthreads();
        #pragma unroll
        for (int q = 0; q < 4; q++) {
            int n = n0 + ty + q * 8, k = k0 + tx;
            bf16 h, l;
            split2(t[tx][ty + q * 8], h, l);
            g_wthi[P.off[mat] + (size_t)n * Kd + k] = h;
            g_wtlo[P.off[mat] + (size_t)n * Kd + k] = l;
        }
    } else {
        int i = (bid - 512) * 256 + threadIdx.x;
        if (i >= N_NODES * F_IN / 4) return;
        float4 v = x4[i];
        bf16 h0, l0, h1, l1, h2, l2, h3, l3;
        split2(v.x, h0, l0); split2(v.y, h1, l1);
        split2(v.z, h2, l2); split2(v.w, h3, l3);
        __nv_bfloat162 hp0{h0, h1}, hp1{h2, h3}, lp0{l0, l1}, lp1{l2, l3};
        *(uint2*)&g_xhi[(size_t)i * 4] = make_uint2(*(uint32_t*)&hp0, *(uint32_t*)&hp1);
        *(uint2*)&g_xlo[(size_t)i * 4] = make_uint2(*(uint32_t*)&lp0, *(uint32_t*)&lp1);
    }
}

// ---------------- segment max over (hi,lo) pairs ----------------------------
__device__ __forceinline__ void accmax(float* m, uint4 H, uint4 L) {
    const uint32_t* hw = &H.x;
    const uint32_t* lw = &L.x;
    #pragma unroll
    for (int w = 0; w < 4; w++) {
        float2 h2 = __bfloat1622float2(*(const __nv_bfloat162*)&hw[w]);
        float2 l2 = __bfloat1622float2(*(const __nv_bfloat162*)&lw[w]);
        m[2 * w]     = fmaxf(m[2 * w],     h2.x + l2.x);
        m[2 * w + 1] = fmaxf(m[2 * w + 1], h2.y + l2.y);
    }
}

template<int F>
__global__ __launch_bounds__(256)
void segmax_kernel(const uint4* __restrict__ hi, const uint4* __restrict__ lo,
                   uint4* __restrict__ ohi, uint4* __restrict__ olo) {
    const int TPN = F / 8;
    int node = blockIdx.x * (256 / TPN) + threadIdx.x / TPN;
    int lane = threadIdx.x % TPN;
    if (node >= N_NODES) return;
    int s = g_rowptr[node], t = g_rowptr[node + 1];
    float m[8];
    #pragma unroll
    for (int k = 0; k < 8; k++) m[k] = -3.402823466e+38f;
    int j = s;
    for (; j + 2 <= t; j += 2) {
        int u0 = g_csrsrc[j], u1 = g_csrsrc[j + 1];
        uint4 H0 = hi[(size_t)u0 * TPN + lane], L0 = lo[(size_t)u0 * TPN + lane];
        uint4 H1 = hi[(size_t)u1 * TPN + lane], L1 = lo[(size_t)u1 * TPN + lane];
        accmax(m, H0, L0);
        accmax(m, H1, L1);
    }
    for (; j < t; j++) {
        int u = g_csrsrc[j];
        accmax(m, hi[(size_t)u * TPN + lane], lo[(size_t)u * TPN + lane]);
    }
    if (t <= s)
        #pragma unroll
        for (int k = 0; k < 8; k++) m[k] = 0.f;
    uint4 OH, OL;
    uint32_t* oh = &OH.x;
    uint32_t* ol = &OL.x;
    #pragma unroll
    for (int w = 0; w < 4; w++) {
        bf16 h0, l0, h1, l1;
        split2(m[2 * w], h0, l0);
        split2(m[2 * w + 1], h1, l1);
        __nv_bfloat162 hp{h0, h1}, lp{l0, l1};
        oh[w] = *(uint32_t*)&hp;
        ol[w] = *(uint32_t*)&lp;
    }
    ohi[(size_t)node * TPN + lane] = OH;
    olo[(size_t)node * TPN + lane] = OL;
}

// ---------------- HMMA split GEMM, cp.async double-buffered ------------------
// CTA 128x64, 8 warps (4m x 2n), warp 32x32, BK=32. Stride 40 bf16 (80B).
// D = Ahi*Bhi + Alo*Bhi + Ahi*Blo (fp32 acc). A,B pre-split bf16.
#define ASTR 40
#define OAH 0
#define OAL 10240
#define OBH 20480
#define OBL 25600
#define STGB 30720
#define GSMEM 61440

template<int KD, bool HEAD>
__global__ __launch_bounds__(256)
void gemm_kernel(const bf16* __restrict__ Agh, const bf16* __restrict__ Agl,
                 const bf16* __restrict__ Axh, const bf16* __restrict__ Axl,
                 const bf16* __restrict__ BlHi, const bf16* __restrict__ BlLo,
                 const bf16* __restrict__ BrHi, const bf16* __restrict__ BrLo,
                 const float* __restrict__ bias,
                 bf16* __restrict__ outHi, bf16* __restrict__ outLo,
                 float* __restrict__ outF) {
    extern __shared__ __align__(16) char dsm[];
    const uint32_t sb = smem_u32(dsm);
    const int tid = threadIdx.x, lane = tid & 31, wid = tid >> 5;
    const int wm = wid & 3, wn = wid >> 2;
    const int bm0 = blockIdx.x * 128, n0 = blockIdx.y * 64;
    const int CPK = KD / 32, NCH = 2 * CPK;

    float acc[2][4][4];
    #pragma unroll
    for (int i = 0; i < 2; i++)
        #pragma unroll
        for (int j = 0; j < 4; j++)
            #pragma unroll
            for (int v = 0; v < 4; v++) acc[i][j][v] = 0.f;

    const uint32_t aRow = wm * 32 + (lane & 15), aCol = (lane >> 4) * 8;
    const uint32_t bRow = wn * 32 + ((lane >> 4) << 3) + (lane & 7);
    const uint32_t bCol = ((lane >> 3) & 1) * 8;

    auto issue = [&](int c) {
        int b = c & 1, pass = c / CPK, kt = (c % CPK) * 32;
        const bf16* Ah = pass ? Axh : Agh;
        const bf16* Al = pass ? Axl : Agl;
        const bf16* Bh = pass ? BrHi : BlHi;
        const bf16* Bl = pass ? BrLo : BlLo;
        uint32_t st = sb + b * STGB;
        #pragma unroll
        for (int q = 0; q < 2; q++) {
            int idx = tid + q * 256, row = idx >> 2, kg = (idx & 3) * 8;
            size_t g = (size_t)(bm0 + row) * KD + kt + kg;
            uint32_t dof = (row * ASTR + kg) * 2;
            cpa(st + OAH + dof, Ah + g);
            cpa(st + OAL + dof, Al + g);
        }
        {
            int row = tid >> 2, kg = (tid & 3) * 8;
            size_t g = (size_t)(n0 + row) * KD + kt + kg;
            uint32_t dof = (row * ASTR + kg) * 2;
            cpa(st + OBH + dof, Bh + g);
            cpa(st + OBL + dof, Bl + g);
        }
        asm volatile("cp.async.commit_group;" ::: "memory");
    };

    issue(0);
    #pragma unroll 1
    for (int c = 0; c < NCH; c++) {
        if (c + 1 < NCH) {
            issue(c + 1);
            asm volatile("cp.async.wait_group 1;" ::: "memory");
        } else {
            asm volatile("cp.async.wait_group 0;" ::: "memory");
        }
        __syncthreads();
        uint32_t st = sb + (c & 1) * STGB;
        #pragma unroll
        for (int ks = 0; ks < 2; ks++) {
            uint32_t ah[2][4], al[2][4], bh[8], bl[8];
            #pragma unroll
            for (int i = 0; i < 2; i++) {
                uint32_t o = ((aRow + i * 16) * ASTR + ks * 16 + aCol) * 2;
                ldsm4(ah[i], st + OAH + o);
                ldsm4(al[i], st + OAL + o);
            }
            #pragma unroll
            for (int jp = 0; jp < 2; jp++) {
                uint32_t o = ((bRow + jp * 16) * ASTR + ks * 16 + bCol) * 2;
                ldsm4(&bh[jp * 4], st + OBH + o);
                ldsm4(&bl[jp * 4], st + OBL + o);
            }
            #pragma unroll
            for (int i = 0; i < 2; i++)
                #pragma unroll
                for (int j = 0; j < 4; j++) {
                    mma_bf16(acc[i][j], ah[i], &bh[j * 2]);
                    mma_bf16(acc[i][j], al[i], &bh[j * 2]);
                    mma_bf16(acc[i][j], ah[i], &bl[j * 2]);
                }
        }
        __syncthreads();
    }

    #pragma unroll
    for (int i = 0; i < 2; i++) {
        #pragma unroll
        for (int j = 0; j < 4; j++) {
            int col = n0 + wn * 32 + j * 8 + (lane & 3) * 2;
            float b0 = bias[col], b1 = bias[col + 1];
            int r0 = bm0 + wm * 32 + i * 16 + (lane >> 2);
            #pragma unroll
            for (int hrow = 0; hrow < 2; hrow++) {
                int r = r0 + hrow * 8;
                if (r >= N_NODES) continue;
                float v0 = fmaxf(acc[i][j][2 * hrow + 0] + b0, 0.f);
                float v1 = fmaxf(acc[i][j][2 * hrow + 1] + b1, 0.f);
                if (HEAD) {
                    *(float2*)&outF[(size_t)r * 256 + col] = make_float2(v0, v1);
                } else {
                    bf16 h0, l0, h1, l1;
                    split2(v0, h0, l0);
                    split2(v1, h1, l1);
                    __nv_bfloat162 hp{h0, h1}, lp{l0, l1};
                    *(uint32_t*)&outHi[(size_t)r * 256 + col] = *(uint32_t*)&hp;
                    *(uint32_t*)&outLo[(size_t)r * 256 + col] = *(uint32_t*)&lp;
                }
            }
        }
    }
}

// ---------------- head dot ----------------
__global__ __launch_bounds__(256)
void head_dot_kernel(const float4* __restrict__ feat, const float* __restrict__ w,
                     const float* __restrict__ b, float* __restrict__ out) {
    int wid = threadIdx.x >> 5, lane = threadIdx.x & 31;
    int row = blockIdx.x * 8 + wid;
    if (row >= N_NODES) return;
    const float4* fr = feat + (size_t)row * 64;
    const float4* w4 = (const float4*)w;
    float s = 0.f;
    #pragma unroll
    for (int q = 0; q < 2; q++) {
        float4 f = fr[lane + q * 32];
        float4 ww = w4[lane + q * 32];
        s += f.x * ww.x + f.y * ww.y + f.z * ww.z + f.w * ww.w;
    }
    #pragma unroll
    for (int off = 16; off; off >>= 1) s += __shfl_xor_sync(~0u, s, off);
    if (lane == 0) out[row] = s + b[0];
}

// ---------------- launcher ----------------
extern "C" void kernel_launch(void* const* d_in, const int* in_sizes, int n_in,
                              void* d_out, int out_size) {
    const float* x   = (const float*)d_in[0];
    const void*  ei  = d_in[1];
    const float *Wl1 = (const float*)d_in[2],  *bl1 = (const float*)d_in[3],
                *Wr1 = (const float*)d_in[4];
    const float *Wl2 = (const float*)d_in[5],  *bl2 = (const float*)d_in[6],
                *Wr2 = (const float*)d_in[7];
    const float *Wla = (const float*)d_in[8],  *bla = (const float*)d_in[9],
                *Wra = (const float*)d_in[10], *Wa  = (const float*)d_in[11],
                *ba  = (const float*)d_in[12];
    const float *Wlm = (const float*)d_in[13], *blm = (const float*)d_in[14],
                *Wrm = (const float*)d_in[15], *Wm  = (const float*)d_in[16],
                *bm  = (const float*)d_in[17];
    float* out = (float*)d_out;

    bf16 *xhi, *xlo, *aghi, *aglo, *h1hi, *h1lo, *h2hi, *h2lo, *whi, *wlo;
    float* f32;
    cudaGetSymbolAddress((void**)&xhi,  g_xhi);
    cudaGetSymbolAddress((void**)&xlo,  g_xlo);
    cudaGetSymbolAddress((void**)&aghi, g_aghi);
    cudaGetSymbolAddress((void**)&aglo, g_aglo);
    cudaGetSymbolAddress((void**)&h1hi, g_h1hi);
    cudaGetSymbolAddress((void**)&h1lo, g_h1lo);
    cudaGetSymbolAddress((void**)&h2hi, g_h2hi);
    cudaGetSymbolAddress((void**)&h2lo, g_h2lo);
    cudaGetSymbolAddress((void**)&f32,  g_f32);
    cudaGetSymbolAddress((void**)&whi,  g_wthi);
    cudaGetSymbolAddress((void**)&wlo,  g_wtlo);

    cudaFuncSetAttribute(gemm_kernel<128, false>, cudaFuncAttributeMaxDynamicSharedMemorySize, GSMEM);
    cudaFuncSetAttribute(gemm_kernel<256, false>, cudaFuncAttributeMaxDynamicSharedMemorySize, GSMEM);
    cudaFuncSetAttribute(gemm_kernel<256, true>,  cudaFuncAttributeMaxDynamicSharedMemorySize, GSMEM);

    const int oL1 = 0, oR1 = 32768, oL2 = 65536, oR2 = 131072,
              oLA = 196608, oRA = 262144, oLM = 327680, oRM = 393216;
    ConvW cw;
    cw.W[0] = Wl1; cw.W[1] = Wr1; cw.W[2] = Wl2; cw.W[3] = Wr2;
    cw.W[4] = Wla; cw.W[5] = Wra; cw.W[6] = Wlm; cw.W[7] = Wrm;
    cw.off[0] = oL1; cw.off[1] = oR1; cw.off[2] = oL2; cw.off[3] = oR2;
    cw.off[4] = oLA; cw.off[5] = oRA; cw.off[6] = oLM; cw.off[7] = oRM;
    cw.K[0] = 128; cw.K[1] = 128;
    for (int i = 2; i < 8; i++) cw.K[i] = 256;

    const int SEG1 = (N_NODES + 15) / 16, SEG2 = (N_NODES + 7) / 8;
    const dim3 GG((N_NODES + 127) / 128, 4);
    const int HD = (N_NODES + 7) / 8;

    conv_kernel<<<512 + XBLKS, 256>>>(cw, (const float4*)x);                     // 0
    hist_kernel<<<(E_EDGES + 511) / 512, 512>>>(ei);                             // 1
    scan_kernel<<<SCAN_BLOCKS, 1024>>>();                                        // 2
    scatter_kernel<<<(E_EDGES + 511) / 512, 512>>>(ei);                          // 3

    segmax_kernel<F_IN><<<SEG1, 256>>>((const uint4*)xhi, (const uint4*)xlo,     // 4
                                       (uint4*)aghi, (uint4*)aglo);
    gemm_kernel<128, false><<<GG, 256, GSMEM>>>(                                 // 5
        aghi, aglo, xhi, xlo, whi + oL1, wlo + oL1, whi + oR1, wlo + oR1,
        bl1, h1hi, h1lo, nullptr);
    segmax_kernel<HID><<<SEG2, 256>>>((const uint4*)h1hi, (const uint4*)h1lo,
                                      (uint4*)aghi, (uint4*)aglo);
    gemm_kernel<256, false><<<GG, 256, GSMEM>>>(
        aghi, aglo, h1hi, h1lo, whi + oL2, wlo + oL2, whi + oR2, wlo + oR2,
        bl2, h2hi, h2lo, nullptr);
    segmax_kernel<HID><<<SEG2, 256>>>((const uint4*)h2hi, (const uint4*)h2lo,
                                      (uint4*)aghi, (uint4*)aglo);
    gemm_kernel<256, true><<<GG, 256, GSMEM>>>(
        aghi, aglo, h2hi, h2lo, whi + oLA, wlo + oLA, whi + oRA, wlo + oRA,
        bla, nullptr, nullptr, f32);
    head_dot_kernel<<<HD, 256>>>((const float4*)f32, Wa, ba, out);
    gemm_kernel<256, true><<<GG, 256, GSMEM>>>(
        aghi, aglo, h2hi, h2lo, whi + oLM, wlo + oLM, whi + oRM, wlo + oRM,
        blm, nullptr, nullptr, f32);
    head_dot_kernel<<<HD, 256>>>((const float4*)f32, Wm, bm, out + N_NODES);
    reset_kernel<<<SCAN_BLOCKS, 1024>>>();
}

// round 14
// speedup vs baseline: 1.1505x; 1.1505x over previous
#include <cuda_runtime.h>
#include <cuda_bf16.h>
#include <cstdint>

using bf16 = __nv_bfloat16;

#define N_NODES 50000
#define E_EDGES 800000
#define F_IN    128
#define HID     256
#define SCAN_BLOCKS 49

__device__ float g_agg[(size_t)N_NODES * HID];
__device__ float g_h1 [(size_t)N_NODES * HID];
__device__ float g_h2 [(size_t)N_NODES * HID];
__device__ bf16  g_wthi[458752];
__device__ bf16  g_wtlo[458752];
__device__ int   g_deg[N_NODES];
__device__ int   g_rowptr[N_NODES + 1];
__device__ int   g_cursor[N_NODES];
__device__ int   g_csrsrc[E_EDGES];
__device__ int   g_flag[SCAN_BLOCKS + 1];
__device__ int   g_pref[SCAN_BLOCKS + 1];

// ---------------- PTX helpers ----------------
__device__ __forceinline__ uint32_t smem_u32(const void* p) {
    uint32_t a;
    asm("{ .reg .u64 t; cvta.to.shared.u64 t, %1; cvt.u32.u64 %0, t; }" : "=r"(a) : "l"(p));
    return a;
}
__device__ __forceinline__ void ldsm4(uint32_t* r, uint32_t addr) {
    asm volatile("ldmatrix.sync.aligned.m8n8.x4.shared.b16 {%0,%1,%2,%3}, [%4];"
                 : "=r"(r[0]), "=r"(r[1]), "=r"(r[2]), "=r"(r[3]) : "r"(addr));
}
__device__ __forceinline__ void mma_bf16(float* c, const uint32_t* a, const uint32_t* b) {
    asm volatile("mma.sync.aligned.m16n8k16.row.col.f32.bf16.bf16.f32 "
                 "{%0,%1,%2,%3}, {%4,%5,%6,%7}, {%8,%9}, {%0,%1,%2,%3};"
                 : "+f"(c[0]), "+f"(c[1]), "+f"(c[2]), "+f"(c[3])
                 : "r"(a[0]), "r"(a[1]), "r"(a[2]), "r"(a[3]), "r"(b[0]), "r"(b[1]));
}
__device__ __forceinline__ void split2(float v, bf16& h, bf16& l) {
    h = __float2bfloat16(v);
    l = __float2bfloat16(v - __bfloat162float(h));
}

// ---------------- CSR build ----------------
__device__ __forceinline__ int detect_is64(const void* ei) {
    __shared__ int s64;
    if (threadIdx.x == 0) {
        const long long* p = (const long long*)ei;
        int ok = 1;
        #pragma unroll 1
        for (int k = 0; k < 128; k++) {
            long long v = p[k];
            if (v < 0 || v >= N_NODES) { ok = 0; break; }
        }
        s64 = ok;
    }
    __syncthreads();
    return s64;
}
__device__ __forceinline__ int load_edge(const void* ei, int idx, int is64) {
    return is64 ? (int)((const long long*)ei)[idx] : ((const int*)ei)[idx];
}

__global__ void hist_kernel(const void* ei) {
    int is64 = detect_is64(ei);
    int e = blockIdx.x * blockDim.x + threadIdx.x;
    if (e < E_EDGES) atomicAdd(&g_deg[load_edge(ei, E_EDGES + e, is64)], 1);
}

__global__ __launch_bounds__(1024)
void scan_kernel() {
    __shared__ int wsum[32];
    __shared__ int s_pref;
    int tid = threadIdx.x, b = blockIdx.x, wid = tid >> 5, lane = tid & 31;
    int i = b * 1024 + tid;
    int v = (i < N_NODES) ? g_deg[i] : 0;
    int incl = v;
    #pragma unroll
    for (int off = 1; off < 32; off <<= 1) {
        int t = __shfl_up_sync(~0u, incl, off);
        if (lane >= off) incl += t;
    }
    if (lane == 31) wsum[wid] = incl;
    __syncthreads();
    if (tid < 32) {
        int x = wsum[tid];
        #pragma unroll
        for (int off = 1; off < 32; off <<= 1) {
            int t = __shfl_up_sync(~0u, x, off);
            if (tid >= off) x += t;
        }
        wsum[tid] = x;
    }
    __syncthreads();
    int excl = (wid ? wsum[wid - 1] : 0) + incl - v;
    if (tid == 0) {
        int total = wsum[31], p = 0;
        if (b > 0) {
            while (atomicAdd(&g_flag[b - 1], 0) == 0) { }
            p = *((volatile int*)&g_pref[b - 1]);
        }
        *((volatile int*)&g_pref[b]) = p + total;
        __threadfence();
        atomicExch(&g_flag[b], 1);
        s_pref = p;
    }
    __syncthreads();
    if (i < N_NODES) { int r = s_pref + excl; g_rowptr[i] = r; g_cursor[i] = r; }
    if (b == 0 && tid == 0) g_rowptr[N_NODES] = E_EDGES;
}

__global__ void scatter_kernel(const void* ei) {
    int is64 = detect_is64(ei);
    int e = blockIdx.x * blockDim.x + threadIdx.x;
    if (e < E_EDGES) {
        int s = load_edge(ei, e, is64);
        int d = load_edge(ei, E_EDGES + e, is64);
        g_csrsrc[atomicAdd(&g_cursor[d], 1)] = s;
    }
}

__global__ void reset_kernel() {
    int i = blockIdx.x * blockDim.x + threadIdx.x;
    if (i < N_NODES) g_deg[i] = 0;
    if (i <= SCAN_BLOCKS) { g_flag[i] = 0; g_pref[i] = 0; }
}

// ---------------- weight transpose + hi/lo split ([n][k], k contiguous) -----
struct ConvW { const float* W[8]; int off[8]; int K[8]; };
__global__ void conv_w_kernel(ConvW P) {
    int mat = blockIdx.z, Kd = P.K[mat];
    if ((int)blockIdx.y * 32 >= Kd) return;
    __shared__ float t[32][33];
    int n0 = blockIdx.x * 32, k0 = blockIdx.y * 32;
    #pragma unroll
    for (int q = 0; q < 4; q++)
        t[threadIdx.y + q * 8][threadIdx.x] =
            P.W[mat][(size_t)(k0 + threadIdx.y + q * 8) * 256 + n0 + threadIdx.x];
    __syncthreads();
    #pragma unroll
    for (int q = 0; q < 4; q++) {
        int n = n0 + threadIdx.y + q * 8, k = k0 + threadIdx.x;
        bf16 h, l;
        split2(t[threadIdx.x][threadIdx.y + q * 8], h, l);
        g_wthi[P.off[mat] + (size_t)n * Kd + k] = h;
        g_wtlo[P.off[mat] + (size_t)n * Kd + k] = l;
    }
}

// ---------------- segment max (fp32, float4 — R12 proven) ----------------
template<int F>
__global__ __launch_bounds__(256)
void segmax_kernel(const float4* __restrict__ in, float4* __restrict__ out) {
    const int TPN = F / 4;
    int node = blockIdx.x * (256 / TPN) + threadIdx.x / TPN;
    int lane = threadIdx.x % TPN;
    if (node >= N_NODES) return;
    int s = g_rowptr[node], t = g_rowptr[node + 1];
    const float NEG = -3.402823466e+38f;
    float4 m = make_float4(NEG, NEG, NEG, NEG);
    int j = s;
    for (; j + 4 <= t; j += 4) {
        int u0 = g_csrsrc[j], u1 = g_csrsrc[j + 1], u2 = g_csrsrc[j + 2], u3 = g_csrsrc[j + 3];
        float4 v0 = in[(size_t)u0 * TPN + lane], v1 = in[(size_t)u1 * TPN + lane];
        float4 v2 = in[(size_t)u2 * TPN + lane], v3 = in[(size_t)u3 * TPN + lane];
        m.x = fmaxf(m.x, fmaxf(fmaxf(v0.x, v1.x), fmaxf(v2.x, v3.x)));
        m.y = fmaxf(m.y, fmaxf(fmaxf(v0.y, v1.y), fmaxf(v2.y, v3.y)));
        m.z = fmaxf(m.z, fmaxf(fmaxf(v0.z, v1.z), fmaxf(v2.z, v3.z)));
        m.w = fmaxf(m.w, fmaxf(fmaxf(v0.w, v1.w), fmaxf(v2.w, v3.w)));
    }
    for (; j < t; j++) {
        float4 v = in[(size_t)g_csrsrc[j] * TPN + lane];
        m.x = fmaxf(m.x, v.x); m.y = fmaxf(m.y, v.y);
        m.z = fmaxf(m.z, v.z); m.w = fmaxf(m.w, v.w);
    }
    if (t <= s) m = make_float4(0.f, 0.f, 0.f, 0.f);
    out[(size_t)node * TPN + lane] = m;
}

// ---------------- HMMA split GEMM, CTA 128x128 (halved A redundancy) --------
// h = relu(Aagg@Wl + Ax@Wr + bias); D = Ahi*Bhi + Alo*Bhi + Ahi*Blo (fp32 acc)
// 8 warps: 4m x 2n, warp tile 32x64. BK=32. Stride 40 bf16 (80B, conflict-free
// for ldmatrix). A converted fp32->hi/lo in kernel (R12-proven path), B
// pre-transposed/split. N-slabs per kernel: 2 (gridDim.y=2) instead of 4.
#define ASTR 40
template<int KD>
__global__ __launch_bounds__(256)
void gemm_kernel(const float* __restrict__ Aagg, const float* __restrict__ Ax,
                 const bf16* __restrict__ BlHi, const bf16* __restrict__ BlLo,
                 const bf16* __restrict__ BrHi, const bf16* __restrict__ BrLo,
                 const float* __restrict__ bias, float* __restrict__ h32) {
    __shared__ __align__(16) bf16 sAh[128 * ASTR];
    __shared__ __align__(16) bf16 sAl[128 * ASTR];
    __shared__ __align__(16) bf16 sBh[128 * ASTR];
    __shared__ __align__(16) bf16 sBl[128 * ASTR];

    const int tid = threadIdx.x, lane = tid & 31, wid = tid >> 5;
    const int wm = wid & 3, wn = wid >> 2;           // 4m x 2n
    const int bm0 = blockIdx.x * 128, n0 = blockIdx.y * 128;
    const uint32_t aBase = smem_u32(sAh), alBase = smem_u32(sAl);
    const uint32_t bBase = smem_u32(sBh), blBase = smem_u32(sBl);

    float acc[2][8][4];
    #pragma unroll
    for (int i = 0; i < 2; i++)
        #pragma unroll
        for (int j = 0; j < 8; j++)
            #pragma unroll
            for (int v = 0; v < 4; v++) acc[i][j][v] = 0.f;

    // ldmatrix source coordinates
    const uint32_t aRow = wm * 32 + (lane & 15), aCol = (lane >> 4) * 8;
    const uint32_t bRowB = wn * 64 + ((lane >> 4) << 3) + (lane & 7);
    const uint32_t bCol = ((lane >> 3) & 1) * 8;

    #pragma unroll 1
    for (int pass = 0; pass < 2; pass++) {
        const float* A = pass ? Ax : Aagg;
        const bf16* Bh = pass ? BrHi : BlHi;
        const bf16* Bl = pass ? BrLo : BlLo;
        #pragma unroll 1
        for (int kt = 0; kt < KD; kt += 32) {
            // A: 128x32 fp32 -> hi/lo bf16 (1024 float4 slots)
            #pragma unroll
            for (int q = 0; q < 4; q++) {
                int idx = tid + q * 256;
                int row = idx >> 3, kg = (idx & 7) * 4;
                int r = bm0 + row;
                float4 v = (r < N_NODES) ? *(const float4*)&A[(size_t)r * KD + kt + kg]
                                         : make_float4(0.f, 0.f, 0.f, 0.f);
                bf16 h0, l0, h1, l1, h2, l2, h3, l3;
                split2(v.x, h0, l0); split2(v.y, h1, l1);
                split2(v.z, h2, l2); split2(v.w, h3, l3);
                __nv_bfloat162 hp0{h0, h1}, hp1{h2, h3}, lp0{l0, l1}, lp1{l2, l3};
                *(uint2*)&sAh[row * ASTR + kg] = make_uint2(*(uint32_t*)&hp0, *(uint32_t*)&hp1);
                *(uint2*)&sAl[row * ASTR + kg] = make_uint2(*(uint32_t*)&lp0, *(uint32_t*)&lp1);
            }
            // B: 128x32 bf16 hi/lo (512 uint4 chunks each)
            #pragma unroll
            for (int q = 0; q < 2; q++) {
                int idx = tid * 2 + q;
                int row = idx >> 2, kg = (idx & 3) * 8;
                const uint4 vh = *(const uint4*)&Bh[(size_t)(n0 + row) * KD + kt + kg];
                const uint4 vl = *(const uint4*)&Bl[(size_t)(n0 + row) * KD + kt + kg];
                *(uint2*)&sBh[row * ASTR + kg]     = make_uint2(vh.x, vh.y);
                *(uint2*)&sBh[row * ASTR + kg + 4] = make_uint2(vh.z, vh.w);
                *(uint2*)&sBl[row * ASTR + kg]     = make_uint2(vl.x, vl.y);
                *(uint2*)&sBl[row * ASTR + kg + 4] = make_uint2(vl.z, vl.w);
            }
            __syncthreads();

            #pragma unroll
            for (int ks = 0; ks < 2; ks++) {
                uint32_t ah[2][4], al[2][4];
                #pragma unroll
                for (int i = 0; i < 2; i++) {
                    uint32_t o = ((aRow + i * 16) * ASTR + ks * 16 + aCol) * 2;
                    ldsm4(ah[i], aBase + o);
                    ldsm4(al[i], alBase + o);
                }
                #pragma unroll
                for (int jp = 0; jp < 4; jp++) {     // 4 chunks of 16 cols
                    uint32_t bh[4], bl[4];
                    uint32_t o = ((bRowB + jp * 16) * ASTR + ks * 16 + bCol) * 2;
                    ldsm4(bh, bBase + o);
                    ldsm4(bl, blBase + o);
                    #pragma unroll
                    for (int i = 0; i < 2; i++)
                        #pragma unroll
                        for (int jj = 0; jj < 2; jj++) {
                            int j = jp * 2 + jj;
                            mma_bf16(acc[i][j], ah[i], &bh[jj * 2]);
                            mma_bf16(acc[i][j], al[i], &bh[jj * 2]);
                            mma_bf16(acc[i][j], ah[i], &bl[jj * 2]);
                        }
                }
            }
            __syncthreads();
        }
    }

    // epilogue: bias + relu, float2 stores
    #pragma unroll
    for (int i = 0; i < 2; i++) {
        #pragma unroll
        for (int j = 0; j < 8; j++) {
            int col = n0 + wn * 64 + j * 8 + (lane & 3) * 2;
            float b0 = bias[col], b1 = bias[col + 1];
            int r0 = bm0 + wm * 32 + i * 16 + (lane >> 2);
            if (r0 < N_NODES) {
                float2 o0;
                o0.x = fmaxf(acc[i][j][0] + b0, 0.f);
                o0.y = fmaxf(acc[i][j][1] + b1, 0.f);
                *(float2*)&h32[(size_t)r0 * 256 + col] = o0;
            }
            int r1 = r0 + 8;
            if (r1 < N_NODES) {
                float2 o1;
                o1.x = fmaxf(acc[i][j][2] + b0, 0.f);
                o1.y = fmaxf(acc[i][j][3] + b1, 0.f);
                *(float2*)&h32[(size_t)r1 * 256 + col] = o1;
            }
        }
    }
}

// ---------------- head dot: out[r] = feat[r,:] . w + b ----------------------
__global__ __launch_bounds__(256)
void head_dot_kernel(const float4* __restrict__ feat, const float* __restrict__ w,
                     const float* __restrict__ b, float* __restrict__ out) {
    int wid = threadIdx.x >> 5, lane = threadIdx.x & 31;
    int row = blockIdx.x * 8 + wid;
    if (row >= N_NODES) return;
    const float4* fr = feat + (size_t)row * 64;
    const float4* w4 = (const float4*)w;
    float s = 0.f;
    #pragma unroll
    for (int q = 0; q < 2; q++) {
        float4 f = fr[lane + q * 32];
        float4 ww = w4[lane + q * 32];
        s += f.x * ww.x + f.y * ww.y + f.z * ww.z + f.w * ww.w;
    }
    #pragma unroll
    for (int off = 16; off; off >>= 1) s += __shfl_xor_sync(~0u, s, off);
    if (lane == 0) out[row] = s + b[0];
}

// ---------------- launcher ----------------
extern "C" void kernel_launch(void* const* d_in, const int* in_sizes, int n_in,
                              void* d_out, int out_size) {
    const float* x   = (const float*)d_in[0];
    const void*  ei  = d_in[1];
    const float *Wl1 = (const float*)d_in[2],  *bl1 = (const float*)d_in[3],
                *Wr1 = (const float*)d_in[4];
    const float *Wl2 = (const float*)d_in[5],  *bl2 = (const float*)d_in[6],
                *Wr2 = (const float*)d_in[7];
    const float *Wla = (const float*)d_in[8],  *bla = (const float*)d_in[9],
                *Wra = (const float*)d_in[10], *Wa  = (const float*)d_in[11],
                *ba  = (const float*)d_in[12];
    const float *Wlm = (const float*)d_in[13], *blm = (const float*)d_in[14],
                *Wrm = (const float*)d_in[15], *Wm  = (const float*)d_in[16],
                *bm  = (const float*)d_in[17];
    float* out = (float*)d_out;

    float *agg, *h1, *h2;
    bf16 *whi, *wlo;
    cudaGetSymbolAddress((void**)&agg, g_agg);
    cudaGetSymbolAddress((void**)&h1,  g_h1);
    cudaGetSymbolAddress((void**)&h2,  g_h2);
    cudaGetSymbolAddress((void**)&whi, g_wthi);
    cudaGetSymbolAddress((void**)&wlo, g_wtlo);

    const int oL1 = 0, oR1 = 32768, oL2 = 65536, oR2 = 131072,
              oLA = 196608, oRA = 262144, oLM = 327680, oRM = 393216;
    ConvW cw;
    cw.W[0] = Wl1; cw.W[1] = Wr1; cw.W[2] = Wl2; cw.W[3] = Wr2;
    cw.W[4] = Wla; cw.W[5] = Wra; cw.W[6] = Wlm; cw.W[7] = Wrm;
    cw.off[0] = oL1; cw.off[1] = oR1; cw.off[2] = oL2; cw.off[3] = oR2;
    cw.off[4] = oLA; cw.off[5] = oRA; cw.off[6] = oLM; cw.off[7] = oRM;
    cw.K[0] = 128; cw.K[1] = 128;
    for (int i = 2; i < 8; i++) cw.K[i] = 256;

    const int SEG1 = (N_NODES + 7) / 8, SEG2 = (N_NODES + 3) / 4;
    const dim3 GG((N_NODES + 127) / 128, 2);   // 391 x 2 n-slabs of 128
    const int HD = (N_NODES + 7) / 8;

    hist_kernel<<<(E_EDGES + 511) / 512, 512>>>(ei);                   // 0
    scan_kernel<<<SCAN_BLOCKS, 1024>>>();                              // 1
    scatter_kernel<<<(E_EDGES + 511) / 512, 512>>>(ei);                // 2
    conv_w_kernel<<<dim3(8, 8, 8), dim3(32, 8)>>>(cw);                 // 3

    segmax_kernel<F_IN><<<SEG1, 256>>>((const float4*)x, (float4*)agg);          // 4
    gemm_kernel<128><<<GG, 256>>>(agg, x, whi + oL1, wlo + oL1,                  // 5
                                  whi + oR1, wlo + oR1, bl1, h1);
    segmax_kernel<HID><<<SEG2, 256>>>((const float4*)h1, (float4*)agg);
    gemm_kernel<256><<<GG, 256>>>(agg, h1, whi + oL2, wlo + oL2,
                                  whi + oR2, wlo + oR2, bl2, h2);
    segmax_kernel<HID><<<SEG2, 256>>>((const float4*)h2, (float4*)agg);
    gemm_kernel<256><<<GG, 256>>>(agg, h2, whi + oLA, wlo + oLA,
                                  whi + oRA, wlo + oRA, bla, h1);
    head_dot_kernel<<<HD, 256>>>((const float4*)h1, Wa, ba, out);
    gemm_kernel<256><<<GG, 256>>>(agg, h2, whi + oLM, wlo + oLM,
                                  whi + oRM, wlo + oRM, blm, h1);
    head_dot_kernel<<<HD, 256>>>((const float4*)h1, Wm, bm, out + N_NODES);
    reset_kernel<<<SCAN_BLOCKS, 1024>>>();
}

// round 16
// speedup vs baseline: 1.5297x; 1.3295x over previous
#include <cuda_runtime.h>
#include <cuda_bf16.h>
#include <cstdint>

using bf16 = __nv_bfloat16;

#define N_NODES 50000
#define E_EDGES 800000
#define F_IN    128
#define HID     256
#define SCAN_BLOCKS 49

__device__ float g_agg[(size_t)N_NODES * HID];
__device__ float g_h1 [(size_t)N_NODES * HID];
__device__ float g_h2 [(size_t)N_NODES * HID];
__device__ bf16  g_wthi[458752];
__device__ bf16  g_wtlo[458752];
__device__ int   g_deg[N_NODES];
__device__ int   g_rowptr[N_NODES + 1];
__device__ int   g_cursor[N_NODES];
__device__ int   g_csrsrc[E_EDGES];
__device__ int   g_flag[SCAN_BLOCKS + 1];
__device__ int   g_pref[SCAN_BLOCKS + 1];

// ---------------- PTX helpers ----------------
__device__ __forceinline__ uint32_t smem_u32(const void* p) {
    uint32_t a;
    asm("{ .reg .u64 t; cvta.to.shared.u64 t, %1; cvt.u32.u64 %0, t; }" : "=r"(a) : "l"(p));
    return a;
}
__device__ __forceinline__ void ldsm4(uint32_t* r, uint32_t addr) {
    asm volatile("ldmatrix.sync.aligned.m8n8.x4.shared.b16 {%0,%1,%2,%3}, [%4];"
                 : "=r"(r[0]), "=r"(r[1]), "=r"(r[2]), "=r"(r[3]) : "r"(addr));
}
__device__ __forceinline__ void mma_bf16(float* c, const uint32_t* a, const uint32_t* b) {
    asm volatile("mma.sync.aligned.m16n8k16.row.col.f32.bf16.bf16.f32 "
                 "{%0,%1,%2,%3}, {%4,%5,%6,%7}, {%8,%9}, {%0,%1,%2,%3};"
                 : "+f"(c[0]), "+f"(c[1]), "+f"(c[2]), "+f"(c[3])
                 : "r"(a[0]), "r"(a[1]), "r"(a[2]), "r"(a[3]), "r"(b[0]), "r"(b[1]));
}
__device__ __forceinline__ void split2(float v, bf16& h, bf16& l) {
    h = __float2bfloat16(v);
    l = __float2bfloat16(v - __bfloat162float(h));
}

// ---------------- CSR build ----------------
__device__ __forceinline__ int detect_is64(const void* ei) {
    __shared__ int s64;
    if (threadIdx.x == 0) {
        const long long* p = (const long long*)ei;
        int ok = 1;
        #pragma unroll 1
        for (int k = 0; k < 128; k++) {
            long long v = p[k];
            if (v < 0 || v >= N_NODES) { ok = 0; break; }
        }
        s64 = ok;
    }
    __syncthreads();
    return s64;
}
__device__ __forceinline__ int load_edge(const void* ei, int idx, int is64) {
    return is64 ? (int)((const long long*)ei)[idx] : ((const int*)ei)[idx];
}

__global__ void hist_kernel(const void* ei) {
    int is64 = detect_is64(ei);
    int e = blockIdx.x * blockDim.x + threadIdx.x;
    if (e < E_EDGES) atomicAdd(&g_deg[load_edge(ei, E_EDGES + e, is64)], 1);
}

__global__ __launch_bounds__(1024)
void scan_kernel() {
    __shared__ int wsum[32];
    __shared__ int s_pref;
    int tid = threadIdx.x, b = blockIdx.x, wid = tid >> 5, lane = tid & 31;
    int i = b * 1024 + tid;
    int v = (i < N_NODES) ? g_deg[i] : 0;
    int incl = v;
    #pragma unroll
    for (int off = 1; off < 32; off <<= 1) {
        int t = __shfl_up_sync(~0u, incl, off);
        if (lane >= off) incl += t;
    }
    if (lane == 31) wsum[wid] = incl;
    __syncthreads();
    if (tid < 32) {
        int x = wsum[tid];
        #pragma unroll
        for (int off = 1; off < 32; off <<= 1) {
            int t = __shfl_up_sync(~0u, x, off);
            if (tid >= off) x += t;
        }
        wsum[tid] = x;
    }
    __syncthreads();
    int excl = (wid ? wsum[wid - 1] : 0) + incl - v;
    if (tid == 0) {
        int total = wsum[31], p = 0;
        if (b > 0) {
            while (atomicAdd(&g_flag[b - 1], 0) == 0) { }
            p = *((volatile int*)&g_pref[b - 1]);
        }
        *((volatile int*)&g_pref[b]) = p + total;
        __threadfence();
        atomicExch(&g_flag[b], 1);
        s_pref = p;
    }
    __syncthreads();
    if (i < N_NODES) { int r = s_pref + excl; g_rowptr[i] = r; g_cursor[i] = r; }
    if (b == 0 && tid == 0) g_rowptr[N_NODES] = E_EDGES;
}

__global__ void scatter_kernel(const void* ei) {
    int is64 = detect_is64(ei);
    int e = blockIdx.x * blockDim.x + threadIdx.x;
    if (e < E_EDGES) {
        int s = load_edge(ei, e, is64);
        int d = load_edge(ei, E_EDGES + e, is64);
        g_csrsrc[atomicAdd(&g_cursor[d], 1)] = s;
    }
}

__global__ void reset_kernel() {
    int i = blockIdx.x * blockDim.x + threadIdx.x;
    if (i < N_NODES) g_deg[i] = 0;
    if (i <= SCAN_BLOCKS) { g_flag[i] = 0; g_pref[i] = 0; }
}

// ---------------- weight transpose + hi/lo split ([n][k], k contiguous) -----
struct ConvW { const float* W[8]; int off[8]; int K[8]; };
__global__ void conv_w_kernel(ConvW P) {
    int mat = blockIdx.z, Kd = P.K[mat];
    if ((int)blockIdx.y * 32 >= Kd) return;
    __shared__ float t[32][33];
    int n0 = blockIdx.x * 32, k0 = blockIdx.y * 32;
    #pragma unroll
    for (int q = 0; q < 4; q++)
        t[threadIdx.y + q * 8][threadIdx.x] =
            P.W[mat][(size_t)(k0 + threadIdx.y + q * 8) * 256 + n0 + threadIdx.x];
    __syncthreads();
    #pragma unroll
    for (int q = 0; q < 4; q++) {
        int n = n0 + threadIdx.y + q * 8, k = k0 + threadIdx.x;
        bf16 h, l;
        split2(t[threadIdx.x][threadIdx.y + q * 8], h, l);
        g_wthi[P.off[mat] + (size_t)n * Kd + k] = h;
        g_wtlo[P.off[mat] + (size_t)n * Kd + k] = l;
    }
}

// ---------------- segment max (fp32, float4 — R12 proven) ----------------
template<int F>
__global__ __launch_bounds__(256)
void segmax_kernel(const float4* __restrict__ in, float4* __restrict__ out) {
    const int TPN = F / 4;
    int node = blockIdx.x * (256 / TPN) + threadIdx.x / TPN;
    int lane = threadIdx.x % TPN;
    if (node >= N_NODES) return;
    int s = g_rowptr[node], t = g_rowptr[node + 1];
    const float NEG = -3.402823466e+38f;
    float4 m = make_float4(NEG, NEG, NEG, NEG);
    int j = s;
    for (; j + 4 <= t; j += 4) {
        int u0 = g_csrsrc[j], u1 = g_csrsrc[j + 1], u2 = g_csrsrc[j + 2], u3 = g_csrsrc[j + 3];
        float4 v0 = in[(size_t)u0 * TPN + lane], v1 = in[(size_t)u1 * TPN + lane];
        float4 v2 = in[(size_t)u2 * TPN + lane], v3 = in[(size_t)u3 * TPN + lane];
        m.x = fmaxf(m.x, fmaxf(fmaxf(v0.x, v1.x), fmaxf(v2.x, v3.x)));
        m.y = fmaxf(m.y, fmaxf(fmaxf(v0.y, v1.y), fmaxf(v2.y, v3.y)));
        m.z = fmaxf(m.z, fmaxf(fmaxf(v0.z, v1.z), fmaxf(v2.z, v3.z)));
        m.w = fmaxf(m.w, fmaxf(fmaxf(v0.w, v1.w), fmaxf(v2.w, v3.w)));
    }
    for (; j < t; j++) {
        float4 v = in[(size_t)g_csrsrc[j] * TPN + lane];
        m.x = fmaxf(m.x, v.x); m.y = fmaxf(m.y, v.y);
        m.z = fmaxf(m.z, v.z); m.w = fmaxf(m.w, v.w);
    }
    if (t <= s) m = make_float4(0.f, 0.f, 0.f, 0.f);
    out[(size_t)node * TPN + lane] = m;
}

// ---------------- HMMA split GEMM, CTA 128x64 (R12) + register prefetch -----
// h = relu(Aagg@Wl + Ax@Wr + bias); D = Ahi*Bhi + Alo*Bhi + Ahi*Blo (fp32 acc)
// 8 warps: 4m x 2n, warp 32x32, BK=32. Stride 40 bf16 (80B, conflict-free).
// Chunk c+1's global loads are issued into registers during chunk c's compute.
#define ASTR 40
template<int KD>
__global__ __launch_bounds__(256)
void gemm_kernel(const float* __restrict__ Aagg, const float* __restrict__ Ax,
                 const bf16* __restrict__ BlHi, const bf16* __restrict__ BlLo,
                 const bf16* __restrict__ BrHi, const bf16* __restrict__ BrLo,
                 const float* __restrict__ bias, float* __restrict__ h32) {
    __shared__ __align__(16) bf16 sAh[128 * ASTR];
    __shared__ __align__(16) bf16 sAl[128 * ASTR];
    __shared__ __align__(16) bf16 sBh[64 * ASTR];
    __shared__ __align__(16) bf16 sBl[64 * ASTR];

    const int tid = threadIdx.x, lane = tid & 31, wid = tid >> 5;
    const int wm = wid & 3, wn = wid >> 2;
    const int bm0 = blockIdx.x * 128, n0 = blockIdx.y * 64;
    const uint32_t aBase = smem_u32(sAh), alBase = smem_u32(sAl);
    const uint32_t bBase = smem_u32(sBh), blBase = smem_u32(sBl);
    const int CPK = KD / 32, NCH = 2 * CPK;

    float acc[2][4][4];
    #pragma unroll
    for (int i = 0; i < 2; i++)
        #pragma unroll
        for (int j = 0; j < 4; j++)
            #pragma unroll
            for (int v = 0; v < 4; v++) acc[i][j][v] = 0.f;

    const uint32_t aRow = wm * 32 + (lane & 15), aCol = (lane >> 4) * 8;
    const uint32_t bRow = wn * 32 + ((lane >> 4) << 3) + (lane & 7);
    const uint32_t bCol = ((lane >> 3) & 1) * 8;

    // per-thread load slots
    const int arow = tid >> 3, akg = (tid & 7) * 4;     // A: 4 rows apart per q
    const int brow = tid >> 2, bkg = (tid & 3) * 8;     // B: one uint4 each

    float4 pa[4];
    uint4 pbh, pbl;

    auto loadregs = [&](int c) {
        int pass = c / CPK, kt = (c % CPK) * 32;
        const float* A = pass ? Ax : Aagg;
        const bf16* Bh = pass ? BrHi : BlHi;
        const bf16* Bl = pass ? BrLo : BlLo;
        #pragma unroll
        for (int q = 0; q < 4; q++) {
            int r = bm0 + arow + q * 32;
            pa[q] = (r < N_NODES) ? *(const float4*)&A[(size_t)r * KD + kt + akg]
                                  : make_float4(0.f, 0.f, 0.f, 0.f);
        }
        pbh = *(const uint4*)&Bh[(size_t)(n0 + brow) * KD + kt + bkg];
        pbl = *(const uint4*)&Bl[(size_t)(n0 + brow) * KD + kt + bkg];
    };

    loadregs(0);
    #pragma unroll 1
    for (int c = 0; c < NCH; c++) {
        // store prefetched regs -> smem (with A conversion)
        #pragma unroll
        for (int q = 0; q < 4; q++) {
            int row = arow + q * 32;
            float4 v = pa[q];
            bf16 h0, l0, h1, l1, h2, l2, h3, l3;
            split2(v.x, h0, l0); split2(v.y, h1, l1);
            split2(v.z, h2, l2); split2(v.w, h3, l3);
            __nv_bfloat162 hp0{h0, h1}, hp1{h2, h3}, lp0{l0, l1}, lp1{l2, l3};
            *(uint2*)&sAh[row * ASTR + akg] = make_uint2(*(uint32_t*)&hp0, *(uint32_t*)&hp1);
            *(uint2*)&sAl[row * ASTR + akg] = make_uint2(*(uint32_t*)&lp0, *(uint32_t*)&lp1);
        }
        *(uint2*)&sBh[brow * ASTR + bkg]     = make_uint2(pbh.x, pbh.y);
        *(uint2*)&sBh[brow * ASTR + bkg + 4] = make_uint2(pbh.z, pbh.w);
        *(uint2*)&sBl[brow * ASTR + bkg]     = make_uint2(pbl.x, pbl.y);
        *(uint2*)&sBl[brow * ASTR + bkg + 4] = make_uint2(pbl.z, pbl.w);
        __syncthreads();

        if (c + 1 < NCH) loadregs(c + 1);   // LDGs overlap compute below

        #pragma unroll
        for (int ks = 0; ks < 2; ks++) {
            uint32_t ah[2][4], al[2][4], bh[8], bl[8];
            #pragma unroll
            for (int i = 0; i < 2; i++) {
                uint32_t o = ((aRow + i * 16) * ASTR + ks * 16 + aCol) * 2;
                ldsm4(ah[i], aBase + o);
                ldsm4(al[i], alBase + o);
            }
            #pragma unroll
            for (int jp = 0; jp < 2; jp++) {
                uint32_t o = ((bRow + jp * 16) * ASTR + ks * 16 + bCol) * 2;
                ldsm4(&bh[jp * 4], bBase + o);
                ldsm4(&bl[jp * 4], blBase + o);
            }
            #pragma unroll
            for (int i = 0; i < 2; i++)
                #pragma unroll
                for (int j = 0; j < 4; j++) {
                    mma_bf16(acc[i][j], ah[i], &bh[j * 2]);
                    mma_bf16(acc[i][j], al[i], &bh[j * 2]);
                    mma_bf16(acc[i][j], ah[i], &bl[j * 2]);
                }
        }
        __syncthreads();
    }

    // epilogue: bias + relu, float2 stores
    #pragma unroll
    for (int i = 0; i < 2; i++) {
        #pragma unroll
        for (int j = 0; j < 4; j++) {
            int col = n0 + wn * 32 + j * 8 + (lane & 3) * 2;
            float b0 = bias[col], b1 = bias[col + 1];
            int r0 = bm0 + wm * 32 + i * 16 + (lane >> 2);
            if (r0 < N_NODES) {
                float2 o0;
                o0.x = fmaxf(acc[i][j][0] + b0, 0.f);
                o0.y = fmaxf(acc[i][j][1] + b1, 0.f);
                *(float2*)&h32[(size_t)r0 * 256 + col] = o0;
            }
            int r1 = r0 + 8;
            if (r1 < N_NODES) {
                float2 o1;
                o1.x = fmaxf(acc[i][j][2] + b0, 0.f);
                o1.y = fmaxf(acc[i][j][3] + b1, 0.f);
                *(float2*)&h32[(size_t)r1 * 256 + col] = o1;
            }
        }
    }
}

// ---------------- head dot: out[r] = feat[r,:] . w + b ----------------------
__global__ __launch_bounds__(256)
void head_dot_kernel(const float4* __restrict__ feat, const float* __restrict__ w,
                     const float* __restrict__ b, float* __restrict__ out) {
    int wid = threadIdx.x >> 5, lane = threadIdx.x & 31;
    int row = blockIdx.x * 8 + wid;
    if (row >= N_NODES) return;
    const float4* fr = feat + (size_t)row * 64;
    const float4* w4 = (const float4*)w;
    float s = 0.f;
    #pragma unroll
    for (int q = 0; q < 2; q++) {
        float4 f = fr[lane + q * 32];
        float4 ww = w4[lane + q * 32];
        s += f.x * ww.x + f.y * ww.y + f.z * ww.z + f.w * ww.w;
    }
    #pragma unroll
    for (int off = 16; off; off >>= 1) s += __shfl_xor_sync(~0u, s, off);
    if (lane == 0) out[row] = s + b[0];
}

// ---------------- launcher ----------------
extern "C" void kernel_launch(void* const* d_in, const int* in_sizes, int n_in,
                              void* d_out, int out_size) {
    const float* x   = (const float*)d_in[0];
    const void*  ei  = d_in[1];
    const float *Wl1 = (const float*)d_in[2],  *bl1 = (const float*)d_in[3],
                *Wr1 = (const float*)d_in[4];
    const float *Wl2 = (const float*)d_in[5],  *bl2 = (const float*)d_in[6],
                *Wr2 = (const float*)d_in[7];
    const float *Wla = (const float*)d_in[8],  *bla = (const float*)d_in[9],
                *Wra = (const float*)d_in[10], *Wa  = (const float*)d_in[11],
                *ba  = (const float*)d_in[12];
    const float *Wlm = (const float*)d_in[13], *blm = (const float*)d_in[14],
                *Wrm = (const float*)d_in[15], *Wm  = (const float*)d_in[16],
                *bm  = (const float*)d_in[17];
    float* out = (float*)d_out;

    float *agg, *h1, *h2;
    bf16 *whi, *wlo;
    cudaGetSymbolAddress((void**)&agg, g_agg);
    cudaGetSymbolAddress((void**)&h1,  g_h1);
    cudaGetSymbolAddress((void**)&h2,  g_h2);
    cudaGetSymbolAddress((void**)&whi, g_wthi);
    cudaGetSymbolAddress((void**)&wlo, g_wtlo);

    const int oL1 = 0, oR1 = 32768, oL2 = 65536, oR2 = 131072,
              oLA = 196608, oRA = 262144, oLM = 327680, oRM = 393216;
    ConvW cw;
    cw.W[0] = Wl1; cw.W[1] = Wr1; cw.W[2] = Wl2; cw.W[3] = Wr2;
    cw.W[4] = Wla; cw.W[5] = Wra; cw.W[6] = Wlm; cw.W[7] = Wrm;
    cw.off[0] = oL1; cw.off[1] = oR1; cw.off[2] = oL2; cw.off[3] = oR2;
    cw.off[4] = oLA; cw.off[5] = oRA; cw.off[6] = oLM; cw.off[7] = oRM;
    cw.K[0] = 128; cw.K[1] = 128;
    for (int i = 2; i < 8; i++) cw.K[i] = 256;

    const int SEG1 = (N_NODES + 7) / 8, SEG2 = (N_NODES + 3) / 4;
    const dim3 GG((N_NODES + 127) / 128, 4);   // R12 config: 391 x 4 slabs of 64
    const int HD = (N_NODES + 7) / 8;

    hist_kernel<<<(E_EDGES + 511) / 512, 512>>>(ei);                   // 0
    scan_kernel<<<SCAN_BLOCKS, 1024>>>();                              // 1
    scatter_kernel<<<(E_EDGES + 511) / 512, 512>>>(ei);                // 2
    conv_w_kernel<<<dim3(8, 8, 8), dim3(32, 8)>>>(cw);                 // 3

    segmax_kernel<F_IN><<<SEG1, 256>>>((const float4*)x, (float4*)agg);          // 4
    gemm_kernel<128><<<GG, 256>>>(agg, x, whi + oL1, wlo + oL1,                  // 5
                                  whi + oR1, wlo + oR1, bl1, h1);
    segmax_kernel<HID><<<SEG2, 256>>>((const float4*)h1, (float4*)agg);
    gemm_kernel<256><<<GG, 256>>>(agg, h1, whi + oL2, wlo + oL2,
                                  whi + oR2, wlo + oR2, bl2, h2);
    segmax_kernel<HID><<<SEG2, 256>>>((const float4*)h2, (float4*)agg);
    gemm_kernel<256><<<GG, 256>>>(agg, h2, whi + oLA, wlo + oLA,
                                  whi + oRA, wlo + oRA, bla, h1);
    head_dot_kernel<<<HD, 256>>>((const float4*)h1, Wa, ba, out);
    gemm_kernel<256><<<GG, 256>>>(agg, h2, whi + oLM, wlo + oLM,
                                  whi + oRM, wlo + oRM, blm, h1);
    head_dot_kernel<<<HD, 256>>>((const float4*)h1, Wm, bm, out + N_NODES);
    reset_kernel<<<SCAN_BLOCKS, 1024>>>();
}

// round 17
// speedup vs baseline: 1.6144x; 1.0554x over previous
#include <cuda_runtime.h>
#include <cuda_bf16.h>
#include <cstdint>

using bf16 = __nv_bfloat16;

#define N_NODES 50000
#define E_EDGES 800000
#define F_IN    128
#define HID     256
#define SCAN_BLOCKS 49

__device__ float g_agg[(size_t)N_NODES * HID];
__device__ float g_h1 [(size_t)N_NODES * HID];
__device__ float g_h2 [(size_t)N_NODES * HID];
__device__ bf16  g_wthi[458752];
__device__ bf16  g_wtlo[458752];
__device__ int   g_deg[N_NODES];
__device__ int   g_rowptr[N_NODES + 1];
__device__ int   g_cursor[N_NODES];
__device__ int   g_csrsrc[E_EDGES];
__device__ int   g_flag[SCAN_BLOCKS + 1];
__device__ int   g_pref[SCAN_BLOCKS + 1];

// ---------------- PTX helpers ----------------
__device__ __forceinline__ uint32_t smem_u32(const void* p) {
    uint32_t a;
    asm("{ .reg .u64 t; cvta.to.shared.u64 t, %1; cvt.u32.u64 %0, t; }" : "=r"(a) : "l"(p));
    return a;
}
__device__ __forceinline__ void ldsm4(uint32_t* r, uint32_t addr) {
    asm volatile("ldmatrix.sync.aligned.m8n8.x4.shared.b16 {%0,%1,%2,%3}, [%4];"
                 : "=r"(r[0]), "=r"(r[1]), "=r"(r[2]), "=r"(r[3]) : "r"(addr));
}
__device__ __forceinline__ void mma_bf16(float* c, const uint32_t* a, const uint32_t* b) {
    asm volatile("mma.sync.aligned.m16n8k16.row.col.f32.bf16.bf16.f32 "
                 "{%0,%1,%2,%3}, {%4,%5,%6,%7}, {%8,%9}, {%0,%1,%2,%3};"
                 : "+f"(c[0]), "+f"(c[1]), "+f"(c[2]), "+f"(c[3])
                 : "r"(a[0]), "r"(a[1]), "r"(a[2]), "r"(a[3]), "r"(b[0]), "r"(b[1]));
}
__device__ __forceinline__ void split2(float v, bf16& h, bf16& l) {
    h = __float2bfloat16(v);
    l = __float2bfloat16(v - __bfloat162float(h));
}

// ---------------- CSR build ----------------
__device__ __forceinline__ int detect_is64(const void* ei) {
    __shared__ int s64;
    if (threadIdx.x == 0) {
        const long long* p = (const long long*)ei;
        int ok = 1;
        #pragma unroll 1
        for (int k = 0; k < 128; k++) {
            long long v = p[k];
            if (v < 0 || v >= N_NODES) { ok = 0; break; }
        }
        s64 = ok;
    }
    __syncthreads();
    return s64;
}
__device__ __forceinline__ int load_edge(const void* ei, int idx, int is64) {
    return is64 ? (int)((const long long*)ei)[idx] : ((const int*)ei)[idx];
}

__global__ void hist_kernel(const void* ei) {
    int is64 = detect_is64(ei);
    int e = blockIdx.x * blockDim.x + threadIdx.x;
    if (e < E_EDGES) atomicAdd(&g_deg[load_edge(ei, E_EDGES + e, is64)], 1);
}

__global__ __launch_bounds__(1024)
void scan_kernel() {
    __shared__ int wsum[32];
    __shared__ int s_pref;
    int tid = threadIdx.x, b = blockIdx.x, wid = tid >> 5, lane = tid & 31;
    int i = b * 1024 + tid;
    int v = (i < N_NODES) ? g_deg[i] : 0;
    int incl = v;
    #pragma unroll
    for (int off = 1; off < 32; off <<= 1) {
        int t = __shfl_up_sync(~0u, incl, off);
        if (lane >= off) incl += t;
    }
    if (lane == 31) wsum[wid] = incl;
    __syncthreads();
    if (tid < 32) {
        int x = wsum[tid];
        #pragma unroll
        for (int off = 1; off < 32; off <<= 1) {
            int t = __shfl_up_sync(~0u, x, off);
            if (tid >= off) x += t;
        }
        wsum[tid] = x;
    }
    __syncthreads();
    int excl = (wid ? wsum[wid - 1] : 0) + incl - v;
    if (tid == 0) {
        int total = wsum[31], p = 0;
        if (b > 0) {
            while (atomicAdd(&g_flag[b - 1], 0) == 0) { }
            p = *((volatile int*)&g_pref[b - 1]);
        }
        *((volatile int*)&g_pref[b]) = p + total;
        __threadfence();
        atomicExch(&g_flag[b], 1);
        s_pref = p;
    }
    __syncthreads();
    if (i < N_NODES) { int r = s_pref + excl; g_rowptr[i] = r; g_cursor[i] = r; }
    if (b == 0 && tid == 0) g_rowptr[N_NODES] = E_EDGES;
}

__global__ void scatter_kernel(const void* ei) {
    int is64 = detect_is64(ei);
    int e = blockIdx.x * blockDim.x + threadIdx.x;
    if (e < E_EDGES) {
        int s = load_edge(ei, e, is64);
        int d = load_edge(ei, E_EDGES + e, is64);
        g_csrsrc[atomicAdd(&g_cursor[d], 1)] = s;
    }
}

__global__ void reset_kernel() {
    int i = blockIdx.x * blockDim.x + threadIdx.x;
    if (i < N_NODES) g_deg[i] = 0;
    if (i <= SCAN_BLOCKS) { g_flag[i] = 0; g_pref[i] = 0; }
}

// ---------------- weight transpose + hi/lo split ([n][k], k contiguous) -----
struct ConvW { const float* W[8]; int off[8]; int K[8]; };
__global__ void conv_w_kernel(ConvW P) {
    int mat = blockIdx.z, Kd = P.K[mat];
    if ((int)blockIdx.y * 32 >= Kd) return;
    __shared__ float t[32][33];
    int n0 = blockIdx.x * 32, k0 = blockIdx.y * 32;
    #pragma unroll
    for (int q = 0; q < 4; q++)
        t[threadIdx.y + q * 8][threadIdx.x] =
            P.W[mat][(size_t)(k0 + threadIdx.y + q * 8) * 256 + n0 + threadIdx.x];
    __syncthreads();
    #pragma unroll
    for (int q = 0; q < 4; q++) {
        int n = n0 + threadIdx.y + q * 8, k = k0 + threadIdx.x;
        bf16 h, l;
        split2(t[threadIdx.x][threadIdx.y + q * 8], h, l);
        g_wthi[P.off[mat] + (size_t)n * Kd + k] = h;
        g_wtlo[P.off[mat] + (size_t)n * Kd + k] = l;
    }
}

// ---------------- segment max (fp32, float4 — proven) ----------------
template<int F>
__global__ __launch_bounds__(256)
void segmax_kernel(const float4* __restrict__ in, float4* __restrict__ out) {
    const int TPN = F / 4;
    int node = blockIdx.x * (256 / TPN) + threadIdx.x / TPN;
    int lane = threadIdx.x % TPN;
    if (node >= N_NODES) return;
    int s = g_rowptr[node], t = g_rowptr[node + 1];
    const float NEG = -3.402823466e+38f;
    float4 m = make_float4(NEG, NEG, NEG, NEG);
    int j = s;
    for (; j + 4 <= t; j += 4) {
        int u0 = g_csrsrc[j], u1 = g_csrsrc[j + 1], u2 = g_csrsrc[j + 2], u3 = g_csrsrc[j + 3];
        float4 v0 = in[(size_t)u0 * TPN + lane], v1 = in[(size_t)u1 * TPN + lane];
        float4 v2 = in[(size_t)u2 * TPN + lane], v3 = in[(size_t)u3 * TPN + lane];
        m.x = fmaxf(m.x, fmaxf(fmaxf(v0.x, v1.x), fmaxf(v2.x, v3.x)));
        m.y = fmaxf(m.y, fmaxf(fmaxf(v0.y, v1.y), fmaxf(v2.y, v3.y)));
        m.z = fmaxf(m.z, fmaxf(fmaxf(v0.z, v1.z), fmaxf(v2.z, v3.z)));
        m.w = fmaxf(m.w, fmaxf(fmaxf(v0.w, v1.w), fmaxf(v2.w, v3.w)));
    }
    for (; j < t; j++) {
        float4 v = in[(size_t)g_csrsrc[j] * TPN + lane];
        m.x = fmaxf(m.x, v.x); m.y = fmaxf(m.y, v.y);
        m.z = fmaxf(m.z, v.z); m.w = fmaxf(m.w, v.w);
    }
    if (t <= s) m = make_float4(0.f, 0.f, 0.f, 0.f);
    out[(size_t)node * TPN + lane] = m;
}

// ---------------- HMMA split GEMM: reg prefetch + double-buffered SMEM ------
// h = relu(Aagg@Wl + Ax@Wr + bias); D = Ahi*Bhi + Alo*Bhi + Ahi*Blo (fp32 acc)
// 8 warps: 4m x 2n, warp 32x32, BK=32. Stride 40 bf16 (80B, conflict-free).
// ONE __syncthreads per chunk: STS(c)->sync->loadregs(c+1)->compute(c).
// Overwrite safety: passing sync(c-1) implies compute(c-2) done (program order),
// and STS(c) reuses chunk c-2's buffer.
#define ASTR 40
#define OAH  0
#define OAL  10240
#define OBH  20480
#define OBL  25600
#define STGB 30720
#define GSMEM 61440

template<int KD>
__global__ __launch_bounds__(256)
void gemm_kernel(const float* __restrict__ Aagg, const float* __restrict__ Ax,
                 const bf16* __restrict__ BlHi, const bf16* __restrict__ BlLo,
                 const bf16* __restrict__ BrHi, const bf16* __restrict__ BrLo,
                 const float* __restrict__ bias, float* __restrict__ h32) {
    extern __shared__ __align__(16) char dsm[];
    const uint32_t sb = smem_u32(dsm);

    const int tid = threadIdx.x, lane = tid & 31, wid = tid >> 5;
    const int wm = wid & 3, wn = wid >> 2;
    const int bm0 = blockIdx.x * 128, n0 = blockIdx.y * 64;
    const int CPK = KD / 32, NCH = 2 * CPK;

    float acc[2][4][4];
    #pragma unroll
    for (int i = 0; i < 2; i++)
        #pragma unroll
        for (int j = 0; j < 4; j++)
            #pragma unroll
            for (int v = 0; v < 4; v++) acc[i][j][v] = 0.f;

    const uint32_t aRow = wm * 32 + (lane & 15), aCol = (lane >> 4) * 8;
    const uint32_t bRow = wn * 32 + ((lane >> 4) << 3) + (lane & 7);
    const uint32_t bCol = ((lane >> 3) & 1) * 8;

    const int arow = tid >> 3, akg = (tid & 7) * 4;
    const int brow = tid >> 2, bkg = (tid & 3) * 8;

    float4 pa[4];
    uint4 pbh, pbl;

    auto loadregs = [&](int c) {
        int pass = c / CPK, kt = (c % CPK) * 32;
        const float* A = pass ? Ax : Aagg;
        const bf16* Bh = pass ? BrHi : BlHi;
        const bf16* Bl = pass ? BrLo : BlLo;
        #pragma unroll
        for (int q = 0; q < 4; q++) {
            int r = bm0 + arow + q * 32;
            pa[q] = (r < N_NODES) ? *(const float4*)&A[(size_t)r * KD + kt + akg]
                                  : make_float4(0.f, 0.f, 0.f, 0.f);
        }
        pbh = *(const uint4*)&Bh[(size_t)(n0 + brow) * KD + kt + bkg];
        pbl = *(const uint4*)&Bl[(size_t)(n0 + brow) * KD + kt + bkg];
    };

    loadregs(0);
    #pragma unroll 1
    for (int c = 0; c < NCH; c++) {
        char* stp = dsm + (c & 1) * STGB;
        const uint32_t st = sb + (c & 1) * STGB;
        // store prefetched regs -> smem buffer c&1 (with A conversion)
        #pragma unroll
        for (int q = 0; q < 4; q++) {
            int row = arow + q * 32;
            float4 v = pa[q];
            bf16 h0, l0, h1, l1, h2, l2, h3, l3;
            split2(v.x, h0, l0); split2(v.y, h1, l1);
            split2(v.z, h2, l2); split2(v.w, h3, l3);
            __nv_bfloat162 hp0{h0, h1}, hp1{h2, h3}, lp0{l0, l1}, lp1{l2, l3};
            *(uint2*)(stp + OAH + (row * ASTR + akg) * 2) =
                make_uint2(*(uint32_t*)&hp0, *(uint32_t*)&hp1);
            *(uint2*)(stp + OAL + (row * ASTR + akg) * 2) =
                make_uint2(*(uint32_t*)&lp0, *(uint32_t*)&lp1);
        }
        *(uint2*)(stp + OBH + (brow * ASTR + bkg) * 2)       = make_uint2(pbh.x, pbh.y);
        *(uint2*)(stp + OBH + (brow * ASTR + bkg + 4) * 2)   = make_uint2(pbh.z, pbh.w);
        *(uint2*)(stp + OBL + (brow * ASTR + bkg) * 2)       = make_uint2(pbl.x, pbl.y);
        *(uint2*)(stp + OBL + (brow * ASTR + bkg + 4) * 2)   = make_uint2(pbl.z, pbl.w);
        __syncthreads();

        if (c + 1 < NCH) loadregs(c + 1);   // LDGs overlap compute below

        #pragma unroll
        for (int ks = 0; ks < 2; ks++) {
            uint32_t ah[2][4], al[2][4], bh[8], bl[8];
            #pragma unroll
            for (int i = 0; i < 2; i++) {
                uint32_t o = ((aRow + i * 16) * ASTR + ks * 16 + aCol) * 2;
                ldsm4(ah[i], st + OAH + o);
                ldsm4(al[i], st + OAL + o);
            }
            #pragma unroll
            for (int jp = 0; jp < 2; jp++) {
                uint32_t o = ((bRow + jp * 16) * ASTR + ks * 16 + bCol) * 2;
                ldsm4(&bh[jp * 4], st + OBH + o);
                ldsm4(&bl[jp * 4], st + OBL + o);
            }
            #pragma unroll
            for (int i = 0; i < 2; i++)
                #pragma unroll
                for (int j = 0; j < 4; j++) {
                    mma_bf16(acc[i][j], ah[i], &bh[j * 2]);
                    mma_bf16(acc[i][j], al[i], &bh[j * 2]);
                    mma_bf16(acc[i][j], ah[i], &bl[j * 2]);
                }
        }
    }

    // epilogue: bias + relu, float2 stores
    #pragma unroll
    for (int i = 0; i < 2; i++) {
        #pragma unroll
        for (int j = 0; j < 4; j++) {
            int col = n0 + wn * 32 + j * 8 + (lane & 3) * 2;
            float b0 = bias[col], b1 = bias[col + 1];
            int r0 = bm0 + wm * 32 + i * 16 + (lane >> 2);
            if (r0 < N_NODES) {
                float2 o0;
                o0.x = fmaxf(acc[i][j][0] + b0, 0.f);
                o0.y = fmaxf(acc[i][j][1] + b1, 0.f);
                *(float2*)&h32[(size_t)r0 * 256 + col] = o0;
            }
            int r1 = r0 + 8;
            if (r1 < N_NODES) {
                float2 o1;
                o1.x = fmaxf(acc[i][j][2] + b0, 0.f);
                o1.y = fmaxf(acc[i][j][3] + b1, 0.f);
                *(float2*)&h32[(size_t)r1 * 256 + col] = o1;
            }
        }
    }
}

// ---------------- head dot: out[r] = feat[r,:] . w + b ----------------------
__global__ __launch_bounds__(256)
void head_dot_kernel(const float4* __restrict__ feat, const float* __restrict__ w,
                     const float* __restrict__ b, float* __restrict__ out) {
    int wid = threadIdx.x >> 5, lane = threadIdx.x & 31;
    int row = blockIdx.x * 8 + wid;
    if (row >= N_NODES) return;
    const float4* fr = feat + (size_t)row * 64;
    const float4* w4 = (const float4*)w;
    float s = 0.f;
    #pragma unroll
    for (int q = 0; q < 2; q++) {
        float4 f = fr[lane + q * 32];
        float4 ww = w4[lane + q * 32];
        s += f.x * ww.x + f.y * ww.y + f.z * ww.z + f.w * ww.w;
    }
    #pragma unroll
    for (int off = 16; off; off >>= 1) s += __shfl_xor_sync(~0u, s, off);
    if (lane == 0) out[row] = s + b[0];
}

// ---------------- launcher ----------------
extern "C" void kernel_launch(void* const* d_in, const int* in_sizes, int n_in,
                              void* d_out, int out_size) {
    const float* x   = (const float*)d_in[0];
    const void*  ei  = d_in[1];
    const float *Wl1 = (const float*)d_in[2],  *bl1 = (const float*)d_in[3],
                *Wr1 = (const float*)d_in[4];
    const float *Wl2 = (const float*)d_in[5],  *bl2 = (const float*)d_in[6],
                *Wr2 = (const float*)d_in[7];
    const float *Wla = (const float*)d_in[8],  *bla = (const float*)d_in[9],
                *Wra = (const float*)d_in[10], *Wa  = (const float*)d_in[11],
                *ba  = (const float*)d_in[12];
    const float *Wlm = (const float*)d_in[13], *blm = (const float*)d_in[14],
                *Wrm = (const float*)d_in[15], *Wm  = (const float*)d_in[16],
                *bm  = (const float*)d_in[17];
    float* out = (float*)d_out;

    float *agg, *h1, *h2;
    bf16 *whi, *wlo;
    cudaGetSymbolAddress((void**)&agg, g_agg);
    cudaGetSymbolAddress((void**)&h1,  g_h1);
    cudaGetSymbolAddress((void**)&h2,  g_h2);
    cudaGetSymbolAddress((void**)&whi, g_wthi);
    cudaGetSymbolAddress((void**)&wlo, g_wtlo);

    cudaFuncSetAttribute(gemm_kernel<128>, cudaFuncAttributeMaxDynamicSharedMemorySize, GSMEM);
    cudaFuncSetAttribute(gemm_kernel<256>, cudaFuncAttributeMaxDynamicSharedMemorySize, GSMEM);

    const int oL1 = 0, oR1 = 32768, oL2 = 65536, oR2 = 131072,
              oLA = 196608, oRA = 262144, oLM = 327680, oRM = 393216;
    ConvW cw;
    cw.W[0] = Wl1; cw.W[1] = Wr1; cw.W[2] = Wl2; cw.W[3] = Wr2;
    cw.W[4] = Wla; cw.W[5] = Wra; cw.W[6] = Wlm; cw.W[7] = Wrm;
    cw.off[0] = oL1; cw.off[1] = oR1; cw.off[2] = oL2; cw.off[3] = oR2;
    cw.off[4] = oLA; cw.off[5] = oRA; cw.off[6] = oLM; cw.off[7] = oRM;
    cw.K[0] = 128; cw.K[1] = 128;
    for (int i = 2; i < 8; i++) cw.K[i] = 256;

    const int SEG1 = (N_NODES + 7) / 8, SEG2 = (N_NODES + 3) / 4;
    const dim3 GG((N_NODES + 127) / 128, 4);
    const int HD = (N_NODES + 7) / 8;

    hist_kernel<<<(E_EDGES + 511) / 512, 512>>>(ei);                   // 0
    scan_kernel<<<SCAN_BLOCKS, 1024>>>();                              // 1
    scatter_kernel<<<(E_EDGES + 511) / 512, 512>>>(ei);                // 2
    conv_w_kernel<<<dim3(8, 8, 8), dim3(32, 8)>>>(cw);                 // 3

    segmax_kernel<F_IN><<<SEG1, 256>>>((const float4*)x, (float4*)agg);          // 4
    gemm_kernel<128><<<GG, 256, GSMEM>>>(agg, x, whi + oL1, wlo + oL1,           // 5
                                         whi + oR1, wlo + oR1, bl1, h1);
    segmax_kernel<HID><<<SEG2, 256>>>((const float4*)h1, (float4*)agg);
    gemm_kernel<256><<<GG, 256, GSMEM>>>(agg, h1, whi + oL2, wlo + oL2,
                                         whi + oR2, wlo + oR2, bl2, h2);
    segmax_kernel<HID><<<SEG2, 256>>>((const float4*)h2, (float4*)agg);
    gemm_kernel<256><<<GG, 256, GSMEM>>>(agg, h2, whi + oLA, wlo + oLA,
                                         whi + oRA, wlo + oRA, bla, h1);
    head_dot_kernel<<<HD, 256>>>((const float4*)h1, Wa, ba, out);
    gemm_kernel<256><<<GG, 256, GSMEM>>>(agg, h2, whi + oLM, wlo + oLM,
                                         whi + oRM, wlo + oRM, blm, h1);
    head_dot_kernel<<<HD, 256>>>((const float4*)h1, Wm, bm, out + N_NODES);
    reset_kernel<<<SCAN_BLOCKS, 1024>>>();
}